// round 10
// baseline (speedup 1.0000x reference)
#include <cuda_runtime.h>
#include <math.h>

#define BMAX 65536
#define HIS 5
#define KINDS 10

// Compact transposed all_feat: 128 scalar rows (64 pairs):
//   rows 0..39   = user,item,age,gender,occ  (w1 cols 0..39)
//   rows 40..127 = his_pool (88)             (w1 cols 120..207)
static __device__ float2 g_allfeat2[64u * BMAX];
static __device__ float2 g_base2[32u * BMAX];      // 64 scalar rows
static __device__ float2 g_h12[64u * BMAX];        // 128 scalar rows
static __device__ float  g_score[HIS * BMAX];

// Precomputed (kk==0 rows zero). [j][o4][kk] float4 layouts:
static __device__ float g_Wc0[64 * 8];             // (W1c-W1b)[:,0:8]
static __device__ float g_Tc[10 * 16 * 20 * 4];
static __device__ float g_Tm[10 * 32 * 20 * 4];

typedef unsigned long long u64;

__device__ __forceinline__ float4 ldg4(const float* p) {
    return __ldg((const float4*)p);
}
__device__ __forceinline__ u64 pack2(float lo, float hi) {
    u64 r; asm("mov.b64 %0,{%1,%2};" : "=l"(r) : "f"(lo), "f"(hi)); return r;
}
__device__ __forceinline__ u64 dup2(float v) {
    u64 r; asm("mov.b64 %0,{%1,%1};" : "=l"(r) : "f"(v)); return r;
}
__device__ __forceinline__ void unpack2(u64 v, float& lo, float& hi) {
    asm("mov.b64 {%0,%1},%2;" : "=f"(lo), "=f"(hi) : "l"(v));
}
__device__ __forceinline__ void fma2(u64& d, u64 a, u64 b) {
    asm("fma.rn.f32x2 %0,%1,%2,%0;" : "+l"(d) : "l"(a), "l"(b));
}

// ---------------------------------------------------------------------------
// prep: 1024 + 12800 + 25600 outputs.
// ---------------------------------------------------------------------------
extern "C" __global__ void prep_tables(const float* __restrict__ act_w1,
                                       const float* __restrict__ mlp_w1,
                                       const float* __restrict__ kind_emb)
{
    int i = blockIdx.x * blockDim.x + threadIdx.x;
    if (i < 1024) {
        if (i < 512) return;
        int t = i - 512;
        int o = t >> 3, d = t & 7;
        const float* r = act_w1 + o * 264;
        g_Wc0[o * 8 + d] = r[176 + d] - r[88 + d];
        return;
    }
    i -= 1024;
    if (i < 12800) {                   // Tc
        int f = i & 3; int r1 = i >> 2;
        int kk = r1 % 20; r1 /= 20;
        int o4 = r1 % 16; int j = r1 / 16;
        int o = 4 * o4 + f;
        float v = 0.f;
        if (kk != 0) {
            const float* r = act_w1 + o * 264 + 8 * (j + 1);
            const float* e = kind_emb + kk * 8;
            #pragma unroll
            for (int d = 0; d < 8; d++)
                v += (r[176 + d] - r[88 + d]) * e[d];
        }
        g_Tc[i] = v;
        return;
    }
    i -= 12800;
    if (i < 25600) {                   // Tm
        int f = i & 3; int r1 = i >> 2;
        int kk = r1 % 20; r1 /= 20;
        int o4 = r1 % 32; int j = r1 / 32;
        int o = 4 * o4 + f;
        float v = 0.f;
        if (kk != 0) {
            const float* r = mlp_w1 + o * 208 + 40 + 8 * j;
            const float* e = kind_emb + kk * 8;
            #pragma unroll
            for (int d = 0; d < 8; d++) v += r[d] * e[d];
        }
        g_Tm[i] = v;
    }
}

// ---------------------------------------------------------------------------
// k0: gathers (rows 0..39) + base = b1 + Wc0@item_w + sum_j Tc[j][:,kk].
// ---------------------------------------------------------------------------
extern "C" __global__ void __launch_bounds__(128, 4)
k0_feat(const int* __restrict__ userid, const int* __restrict__ itemid,
        const int* __restrict__ user_age, const int* __restrict__ gender,
        const int* __restrict__ user_occ, const int* __restrict__ item_kind,
        const float* __restrict__ user_emb, const float* __restrict__ item_emb,
        const float* __restrict__ age_emb, const float* __restrict__ gender_emb,
        const float* __restrict__ occ_emb,
        const float* __restrict__ act_b1, int B)
{
    __shared__ float sWc0[64 * 8];
    for (int idx = threadIdx.x; idx < 512; idx += blockDim.x) sWc0[idx] = g_Wc0[idx];
    __syncthreads();

    int b = blockIdx.x * blockDim.x + threadIdx.x;
    if (b >= B) return;
    size_t sB = (size_t)B;

    float4 iv0, iv1;
    {
        const float* p = user_emb + (size_t)userid[b] * 8;
        float4 a = ldg4(p), c = ldg4(p + 4);
        float2* q = g_allfeat2 + (size_t)b;
        q[0] = make_float2(a.x, a.y); q[sB] = make_float2(a.z, a.w);
        q[2*sB] = make_float2(c.x, c.y); q[3*sB] = make_float2(c.z, c.w);

        p = item_emb + (size_t)itemid[b] * 8;
        iv0 = ldg4(p); iv1 = ldg4(p + 4);
        q[4*sB] = make_float2(iv0.x, iv0.y); q[5*sB] = make_float2(iv0.z, iv0.w);
        q[6*sB] = make_float2(iv1.x, iv1.y); q[7*sB] = make_float2(iv1.z, iv1.w);

        p = age_emb + (size_t)user_age[b] * 8;
        a = ldg4(p); c = ldg4(p + 4);
        q[8*sB] = make_float2(a.x, a.y); q[9*sB] = make_float2(a.z, a.w);
        q[10*sB] = make_float2(c.x, c.y); q[11*sB] = make_float2(c.z, c.w);

        p = gender_emb + (size_t)gender[b] * 8;
        a = ldg4(p); c = ldg4(p + 4);
        q[12*sB] = make_float2(a.x, a.y); q[13*sB] = make_float2(a.z, a.w);
        q[14*sB] = make_float2(c.x, c.y); q[15*sB] = make_float2(c.z, c.w);

        p = occ_emb + (size_t)user_occ[b] * 8;
        a = ldg4(p); c = ldg4(p + 4);
        q[16*sB] = make_float2(a.x, a.y); q[17*sB] = make_float2(a.z, a.w);
        q[18*sB] = make_float2(c.x, c.y); q[19*sB] = make_float2(c.z, c.w);
    }

    float acc[64];
    #pragma unroll
    for (int o = 0; o < 64; o++) acc[o] = __ldg(act_b1 + o);

    #pragma unroll
    for (int o = 0; o < 64; o++) {
        float4 w0 = *(const float4*)(sWc0 + o * 8);
        float4 w1 = *(const float4*)(sWc0 + o * 8 + 4);
        acc[o] += w0.x*iv0.x + w0.y*iv0.y + w0.z*iv0.z + w0.w*iv0.w
                + w1.x*iv1.x + w1.y*iv1.y + w1.z*iv1.z + w1.w*iv1.w;
    }

    #pragma unroll 1
    for (int j = 0; j < 10; j++) {
        int kk = item_kind[b * KINDS + j];
        const float4* t = (const float4*)g_Tc + (size_t)(j * 16) * 20 + kk;
        #pragma unroll
        for (int o4 = 0; o4 < 16; o4++) {
            float4 v = __ldg(t + o4 * 20);
            acc[4*o4+0] += v.x; acc[4*o4+1] += v.y;
            acc[4*o4+2] += v.z; acc[4*o4+3] += v.w;
        }
    }

    float2* bp = g_base2 + (size_t)b;
    #pragma unroll
    for (int o = 0; o < 32; o++)
        bp[(size_t)o * sB] = make_float2(acc[2*o], acc[2*o + 1]);
}

// ---------------------------------------------------------------------------
// k1s: all 5 attention scores; output-pair packed fma.rn.f32x2.
// smem weight layout: sWa2[k][o2] = (Wa[2o2][k], Wa[2o2+1][k]) as u64.
// ---------------------------------------------------------------------------
extern "C" __global__ void __launch_bounds__(128, 3)
k1s_score(const int* __restrict__ his_id, const int* __restrict__ his_kind,
          const float* __restrict__ item_emb, const float* __restrict__ kind_emb,
          const float* __restrict__ act_w1,
          const float* __restrict__ act_w2, const float* __restrict__ act_b2,
          const float* __restrict__ act_w3, const float* __restrict__ act_b3,
          int B)
{
    __shared__ u64 sWa2[88 * 32];    // [k][o2] pairs, 22.5KB
    __shared__ u64 sW2p[64 * 16];    // [k][o2] pairs, 8KB
    __shared__ float sB2[32];
    __shared__ float sW3[32];
    __shared__ float sB3s;

    for (int idx = threadIdx.x; idx < 88 * 32; idx += blockDim.x) {
        int k = idx >> 5, o2 = idx & 31;
        const float* r0 = act_w1 + (2*o2) * 264;
        const float* r1 = act_w1 + (2*o2 + 1) * 264;
        sWa2[idx] = pack2(r0[k] + r0[88 + k], r1[k] + r1[88 + k]);
    }
    for (int idx = threadIdx.x; idx < 64 * 16; idx += blockDim.x) {
        int k = idx >> 4, o2 = idx & 15;
        sW2p[idx] = pack2(act_w2[(2*o2) * 64 + k], act_w2[(2*o2 + 1) * 64 + k]);
    }
    if (threadIdx.x < 32) { sB2[threadIdx.x] = act_b2[threadIdx.x];
                            sW3[threadIdx.x] = act_w3[threadIdx.x]; }
    if (threadIdx.x == 0) sB3s = act_b3[0];
    __syncthreads();

    int b = blockIdx.x * blockDim.x + threadIdx.x;
    if (b >= B) return;
    size_t sB = (size_t)B;

    #pragma unroll 1
    for (int s = 0; s < HIS; s++) {
        u64 acc[32];
        {
            const float2* bp = g_base2 + (size_t)b;
            #pragma unroll
            for (int o = 0; o < 32; o++) {
                float2 v = bp[(size_t)o * sB];
                acc[o] = pack2(v.x, v.y);
            }
        }

        int hid = his_id[b * HIS + s];
        #pragma unroll 1
        for (int j = 0; j < 11; j++) {
            float e[8];
            if (j == 0) {
                const float* p = item_emb + (size_t)hid * 8;
                float4 v0 = ldg4(p), v1 = ldg4(p + 4);
                e[0]=v0.x; e[1]=v0.y; e[2]=v0.z; e[3]=v0.w;
                e[4]=v1.x; e[5]=v1.y; e[6]=v1.z; e[7]=v1.w;
            } else {
                int kk = his_kind[(b * HIS + s) * KINDS + (j - 1)];
                const float* p = kind_emb + (size_t)kk * 8;
                float4 v0 = ldg4(p), v1 = ldg4(p + 4);
                float m = (kk != 0) ? 1.f : 0.f;
                e[0]=v0.x*m; e[1]=v0.y*m; e[2]=v0.z*m; e[3]=v0.w*m;
                e[4]=v1.x*m; e[5]=v1.y*m; e[6]=v1.z*m; e[7]=v1.w*m;
            }
            const u64* wk = sWa2 + (j * 8) * 32;
            #pragma unroll
            for (int kd = 0; kd < 8; kd++) {
                u64 ad = dup2(e[kd]);
                const ulonglong2* wr = (const ulonglong2*)(wk + kd * 32);
                #pragma unroll
                for (int q = 0; q < 16; q++) {
                    ulonglong2 w = wr[q];
                    fma2(acc[2*q],     w.x, ad);
                    fma2(acc[2*q + 1], w.y, ad);
                }
            }
        }

        // layer 2: consume h on the fly from acc pairs
        u64 acc2[16];
        #pragma unroll
        for (int o2 = 0; o2 < 16; o2++) acc2[o2] = pack2(sB2[2*o2], sB2[2*o2+1]);
        #pragma unroll 1
        for (int p = 0; p < 32; p++) {
            float lo, hi; unpack2(acc[p], lo, hi);
            u64 d0 = dup2(fmaxf(lo, 0.f));
            u64 d1 = dup2(fmaxf(hi, 0.f));
            const ulonglong2* w0 = (const ulonglong2*)(sW2p + (2*p) * 16);
            const ulonglong2* w1 = (const ulonglong2*)(sW2p + (2*p + 1) * 16);
            #pragma unroll
            for (int q = 0; q < 8; q++) {
                ulonglong2 a = w0[q], c = w1[q];
                fma2(acc2[2*q],     a.x, d0);
                fma2(acc2[2*q + 1], a.y, d0);
                fma2(acc2[2*q],     c.x, d1);
                fma2(acc2[2*q + 1], c.y, d1);
            }
        }

        float sc = sB3s;
        #pragma unroll
        for (int p = 0; p < 16; p++) {
            float lo, hi; unpack2(acc2[p], lo, hi);
            sc += sW3[2*p] * fmaxf(lo, 0.f) + sW3[2*p+1] * fmaxf(hi, 0.f);
        }
        g_score[(size_t)s * sB + (size_t)b] = sc;
    }
}

// ---------------------------------------------------------------------------
// k2: his_pool -> compact rows 40..127.
// ---------------------------------------------------------------------------
extern "C" __global__ void __launch_bounds__(128, 4)
k2_pool(const int* __restrict__ his_id, const int* __restrict__ his_kind,
        const float* __restrict__ item_emb, const float* __restrict__ kind_emb,
        int B)
{
    int b = blockIdx.x * blockDim.x + threadIdx.x;
    if (b >= B) return;
    size_t sB = (size_t)B;

    float poolL[88];
    #pragma unroll
    for (int d = 0; d < 88; d++) poolL[d] = 0.f;

    #pragma unroll 1
    for (int s = 0; s < HIS; s++) {
        float sc = g_score[(size_t)s * sB + (size_t)b];
        int hid = his_id[b * HIS + s];
        {
            const float* p = item_emb + (size_t)hid * 8;
            float4 v0 = ldg4(p), v1 = ldg4(p + 4);
            poolL[0] += v0.x*v0.x*sc; poolL[1] += v0.y*v0.y*sc;
            poolL[2] += v0.z*v0.z*sc; poolL[3] += v0.w*v0.w*sc;
            poolL[4] += v1.x*v1.x*sc; poolL[5] += v1.y*v1.y*sc;
            poolL[6] += v1.z*v1.z*sc; poolL[7] += v1.w*v1.w*sc;
        }
        #pragma unroll
        for (int j = 0; j < 10; j++) {
            int kk = his_kind[(b * HIS + s) * KINDS + j];
            const float* p = kind_emb + (size_t)kk * 8;
            float4 v0 = ldg4(p), v1 = ldg4(p + 4);
            float fm = (kk != 0) ? sc : 0.f;
            int pp = 8 + j * 8;
            poolL[pp+0] += v0.x*v0.x*fm; poolL[pp+1] += v0.y*v0.y*fm;
            poolL[pp+2] += v0.z*v0.z*fm; poolL[pp+3] += v0.w*v0.w*fm;
            poolL[pp+4] += v1.x*v1.x*fm; poolL[pp+5] += v1.y*v1.y*fm;
            poolL[pp+6] += v1.z*v1.z*fm; poolL[pp+7] += v1.w*v1.w*fm;
        }
    }
    float2* p = g_allfeat2 + (size_t)20 * sB + (size_t)b;
    #pragma unroll
    for (int d = 0; d < 44; d++)
        p[(size_t)d * sB] = make_float2(poolL[2*d], poolL[2*d + 1]);
}

// ---------------------------------------------------------------------------
// k3: h1 = relu(w1 @ all_feat + b1). 2 samples/thread, 32-output chunks.
// ---------------------------------------------------------------------------
extern "C" __global__ void __launch_bounds__(128, 4)
k3_h1(const float* __restrict__ mlp_w1, const float* __restrict__ mlp_b1,
      const int* __restrict__ item_kind, int B)
{
    int t = blockIdx.x * blockDim.x + threadIdx.x;
    int b0 = 2 * t;
    if (b0 >= B) return;
    int c = blockIdx.y;
    size_t sB = (size_t)B;

    float acc0[32], acc1[32];
    #pragma unroll
    for (int o = 0; o < 32; o++) {
        float bi = __ldg(mlp_b1 + 32*c + o);
        acc0[o] = bi; acc1[o] = bi;
    }

    const float* wbase = mlp_w1 + (size_t)(32 * c) * 208;
    const float2* ab = g_allfeat2 + (size_t)b0;

    #pragma unroll 1
    for (int dc = 0; dc < 32; dc++) {
        float4 A0 = *(const float4*)(ab + (size_t)(2*dc) * sB);
        float4 A1 = *(const float4*)(ab + (size_t)(2*dc + 1) * sB);
        int col = (dc < 10) ? 4*dc : 4*dc + 80;
        const float* wb = wbase + col;
        #pragma unroll
        for (int o = 0; o < 32; o++) {
            float4 w = ldg4(wb + o * 208);
            acc0[o] += w.x*A0.x + w.y*A0.y + w.z*A1.x + w.w*A1.y;
            acc1[o] += w.x*A0.z + w.y*A0.w + w.z*A1.z + w.w*A1.w;
        }
    }

    #pragma unroll 1
    for (int j = 0; j < 10; j++) {
        int ka = item_kind[b0 * KINDS + j];
        int kb = item_kind[(b0 + 1) * KINDS + j];
        const float4* ta = (const float4*)g_Tm + (size_t)(j * 32 + 8 * c) * 20 + ka;
        const float4* tb = (const float4*)g_Tm + (size_t)(j * 32 + 8 * c) * 20 + kb;
        #pragma unroll
        for (int q4 = 0; q4 < 8; q4++) {
            float4 va = __ldg(ta + q4 * 20);
            float4 vb = __ldg(tb + q4 * 20);
            acc0[4*q4+0] += va.x; acc0[4*q4+1] += va.y;
            acc0[4*q4+2] += va.z; acc0[4*q4+3] += va.w;
            acc1[4*q4+0] += vb.x; acc1[4*q4+1] += vb.y;
            acc1[4*q4+2] += vb.z; acc1[4*q4+3] += vb.w;
        }
    }

    float2* hp = g_h12 + (size_t)(16 * c) * sB + (size_t)b0;
    #pragma unroll
    for (int o = 0; o < 16; o++) {
        float4 v = make_float4(fmaxf(acc0[2*o], 0.f), fmaxf(acc0[2*o+1], 0.f),
                               fmaxf(acc1[2*o], 0.f), fmaxf(acc1[2*o+1], 0.f));
        *(float4*)(hp + (size_t)o * sB) = v;
    }
}

// ---------------------------------------------------------------------------
// k4: layers 2..4 + sigmoid, output-pair packed fma.rn.f32x2.
// ---------------------------------------------------------------------------
extern "C" __global__ void __launch_bounds__(128, 3)
k4_out(const float* __restrict__ mlp_w2, const float* __restrict__ mlp_b2,
       const float* __restrict__ mlp_w3, const float* __restrict__ mlp_b3,
       const float* __restrict__ mlp_w4, const float* __restrict__ mlp_b4,
       float* __restrict__ out, int B)
{
    __shared__ u64 sW2p[128 * 32];   // [k][o2] pairs, 32KB
    __shared__ u64 sW3p[64 * 16];    // [k][o2] pairs, 8KB
    __shared__ float sW4[32];
    __shared__ float sB2[64];
    __shared__ float sB3[32];
    __shared__ float sB4s;

    for (int idx = threadIdx.x; idx < 128 * 32; idx += blockDim.x) {
        int k = idx >> 5, o2 = idx & 31;
        sW2p[idx] = pack2(mlp_w2[(2*o2) * 128 + k], mlp_w2[(2*o2 + 1) * 128 + k]);
    }
    for (int idx = threadIdx.x; idx < 64 * 16; idx += blockDim.x) {
        int k = idx >> 4, o2 = idx & 15;
        sW3p[idx] = pack2(mlp_w3[(2*o2) * 64 + k], mlp_w3[(2*o2 + 1) * 64 + k]);
    }
    if (threadIdx.x < 64)  sB2[threadIdx.x] = mlp_b2[threadIdx.x];
    if (threadIdx.x < 32)  { sB3[threadIdx.x] = mlp_b3[threadIdx.x];
                             sW4[threadIdx.x] = mlp_w4[threadIdx.x]; }
    if (threadIdx.x == 0) sB4s = mlp_b4[0];
    __syncthreads();

    int b = blockIdx.x * blockDim.x + threadIdx.x;
    if (b >= B) return;
    size_t sB = (size_t)B;

    u64 acc2[32];
    #pragma unroll
    for (int o2 = 0; o2 < 32; o2++) acc2[o2] = pack2(sB2[2*o2], sB2[2*o2+1]);

    const float2* hp = g_h12 + (size_t)b;
    #pragma unroll 1
    for (int kk2 = 0; kk2 < 64; kk2++) {        // h1 rows 2kk2, 2kk2+1
        float2 u = hp[(size_t)kk2 * sB];
        u64 d0 = dup2(u.x), d1 = dup2(u.y);
        const ulonglong2* w0 = (const ulonglong2*)(sW2p + (2*kk2) * 32);
        const ulonglong2* w1 = (const ulonglong2*)(sW2p + (2*kk2 + 1) * 32);
        #pragma unroll
        for (int q = 0; q < 16; q++) {
            ulonglong2 a = w0[q], c = w1[q];
            fma2(acc2[2*q],     a.x, d0);
            fma2(acc2[2*q + 1], a.y, d0);
            fma2(acc2[2*q],     c.x, d1);
            fma2(acc2[2*q + 1], c.y, d1);
        }
    }

    u64 acc3[16];
    #pragma unroll
    for (int o2 = 0; o2 < 16; o2++) acc3[o2] = pack2(sB3[2*o2], sB3[2*o2+1]);
    #pragma unroll 1
    for (int p = 0; p < 32; p++) {
        float lo, hi; unpack2(acc2[p], lo, hi);
        u64 d0 = dup2(fmaxf(lo, 0.f));
        u64 d1 = dup2(fmaxf(hi, 0.f));
        const ulonglong2* w0 = (const ulonglong2*)(sW3p + (2*p) * 16);
        const ulonglong2* w1 = (const ulonglong2*)(sW3p + (2*p + 1) * 16);
        #pragma unroll
        for (int q = 0; q < 8; q++) {
            ulonglong2 a = w0[q], c = w1[q];
            fma2(acc3[2*q],     a.x, d0);
            fma2(acc3[2*q + 1], a.y, d0);
            fma2(acc3[2*q],     c.x, d1);
            fma2(acc3[2*q + 1], c.y, d1);
        }
    }

    float logit = sB4s;
    #pragma unroll
    for (int p = 0; p < 16; p++) {
        float lo, hi; unpack2(acc3[p], lo, hi);
        logit += sW4[2*p] * fmaxf(lo, 0.f) + sW4[2*p+1] * fmaxf(hi, 0.f);
    }
    out[b] = 1.f / (1.f + expf(-logit));
}

// ---------------------------------------------------------------------------
extern "C" void kernel_launch(void* const* d_in, const int* in_sizes, int n_in,
                              void* d_out, int out_size)
{
    const int*   userid   = (const int*)d_in[0];
    const int*   itemid   = (const int*)d_in[1];
    const int*   user_age = (const int*)d_in[2];
    const int*   gender   = (const int*)d_in[3];
    const int*   user_occ = (const int*)d_in[4];
    const int*   item_kind= (const int*)d_in[5];
    const int*   his_id   = (const int*)d_in[6];
    const int*   his_kind = (const int*)d_in[7];
    const float* user_emb = (const float*)d_in[8];
    const float* item_emb = (const float*)d_in[9];
    const float* age_emb  = (const float*)d_in[10];
    const float* gen_emb  = (const float*)d_in[11];
    const float* occ_emb  = (const float*)d_in[12];
    const float* kind_emb = (const float*)d_in[13];
    const float* act_w1 = (const float*)d_in[14];
    const float* act_b1 = (const float*)d_in[15];
    const float* act_w2 = (const float*)d_in[16];
    const float* act_b2 = (const float*)d_in[17];
    const float* act_w3 = (const float*)d_in[18];
    const float* act_b3 = (const float*)d_in[19];
    const float* mlp_w1 = (const float*)d_in[20];
    const float* mlp_b1 = (const float*)d_in[21];
    const float* mlp_w2 = (const float*)d_in[22];
    const float* mlp_b2 = (const float*)d_in[23];
    const float* mlp_w3 = (const float*)d_in[24];
    const float* mlp_b3 = (const float*)d_in[25];
    const float* mlp_w4 = (const float*)d_in[26];
    const float* mlp_b4 = (const float*)d_in[27];

    int B = in_sizes[0];
    int nb = (B + 127) / 128;

    prep_tables<<<154, 256>>>(act_w1, mlp_w1, kind_emb);

    k0_feat<<<nb, 128>>>(userid, itemid, user_age, gender, user_occ, item_kind,
                         user_emb, item_emb, age_emb, gen_emb, occ_emb,
                         act_b1, B);

    k1s_score<<<nb, 128>>>(his_id, his_kind, item_emb, kind_emb, act_w1,
                           act_w2, act_b2, act_w3, act_b3, B);

    k2_pool<<<nb, 128>>>(his_id, his_kind, item_emb, kind_emb, B);

    k3_h1<<<dim3((B/2 + 127) / 128, 4), 128>>>(mlp_w1, mlp_b1, item_kind, B);

    k4_out<<<nb, 128>>>(mlp_w2, mlp_b2, mlp_w3, mlp_b3, mlp_w4, mlp_b4,
                        (float*)d_out, B);
}

// round 11
// speedup vs baseline: 1.3227x; 1.3227x over previous
#include <cuda_runtime.h>
#include <cuda_fp16.h>
#include <mma.h>
#include <math.h>

using namespace nvcuda;

#define BMAX 65536
#define HIS 5
#define KINDS 10

// ---------------------------------------------------------------------------
// Device scratch
// ---------------------------------------------------------------------------
// all_feat as split fp16, transposed, feature-pair packed:
//   g_af2h[rp][b] = half2(feat[2rp], feat[2rp+1]) high part; g_af2l low part.
// Feature rows: 0..39 user/item/age/gender/occ, 40..119 kind, 120..207 pool.
static __device__ __half2 g_af2h[104u * BMAX];
static __device__ __half2 g_af2l[104u * BMAX];
static __device__ float2  g_base2[32u * BMAX];     // 64 scalar rows fp32
static __device__ float   g_score[HIS * BMAX];

// Tables / prepped weights
static __device__ float  g_Wc0[64 * 8];            // (W1c-W1b)[:,0:8]
static __device__ float  g_Tc[10 * 16 * 20 * 4];   // [j][o4][kk] float4
// Transposed split fp16 weights: [k][n] layouts
static __device__ __half g_w1th[208 * 128];
static __device__ __half g_w1tl[208 * 128];
static __device__ __half g_w2th[128 * 64];
static __device__ __half g_w2tl[128 * 64];
static __device__ __half g_w3th[64 * 32];
static __device__ __half g_w3tl[64 * 32];

__device__ __forceinline__ float4 ldg4(const float* p) {
    return __ldg((const float4*)p);
}

__device__ __forceinline__ void st_feat(int B, int b, int rp, float x, float y) {
    __half hx = __float2half_rn(x), hy = __float2half_rn(y);
    float lx = x - __half2float(hx), ly = y - __half2float(hy);
    g_af2h[(size_t)rp * (size_t)B + (size_t)b] = __halves2half2(hx, hy);
    g_af2l[(size_t)rp * (size_t)B + (size_t)b] =
        __halves2half2(__float2half_rn(lx), __float2half_rn(ly));
}

__device__ __forceinline__ void st8(int B, int b, int rp, float4 v0, float4 v1) {
    st_feat(B, b, rp + 0, v0.x, v0.y);
    st_feat(B, b, rp + 1, v0.z, v0.w);
    st_feat(B, b, rp + 2, v1.x, v1.y);
    st_feat(B, b, rp + 3, v1.z, v1.w);
}

// ---------------------------------------------------------------------------
// prep: Wc0 (512) + Tc (12800) + w1t (26624) + w2t (8192) + w3t (2048)
// ---------------------------------------------------------------------------
extern "C" __global__ void prep_tables(const float* __restrict__ act_w1,
                                       const float* __restrict__ mlp_w1,
                                       const float* __restrict__ mlp_w2,
                                       const float* __restrict__ mlp_w3,
                                       const float* __restrict__ kind_emb)
{
    int i = blockIdx.x * blockDim.x + threadIdx.x;
    if (i < 512) {
        int o = i >> 3, d = i & 7;
        const float* r = act_w1 + o * 264;
        g_Wc0[o * 8 + d] = r[176 + d] - r[88 + d];
        return;
    }
    i -= 512;
    if (i < 12800) {
        int f = i & 3; int r1 = i >> 2;
        int kk = r1 % 20; r1 /= 20;
        int o4 = r1 % 16; int j = r1 / 16;
        int o = 4 * o4 + f;
        float v = 0.f;
        if (kk != 0) {
            const float* r = act_w1 + o * 264 + 8 * (j + 1);
            const float* e = kind_emb + kk * 8;
            #pragma unroll
            for (int d = 0; d < 8; d++)
                v += (r[176 + d] - r[88 + d]) * e[d];
        }
        g_Tc[i] = v;
        return;
    }
    i -= 12800;
    if (i < 26624) {                    // w1t: [k=208][n=128]
        int k = i >> 7, n = i & 127;
        float w = mlp_w1[n * 208 + k];
        __half h = __float2half_rn(w);
        g_w1th[i] = h;
        g_w1tl[i] = __float2half_rn(w - __half2float(h));
        return;
    }
    i -= 26624;
    if (i < 8192) {                     // w2t: [k=128][n=64]
        int k = i >> 6, n = i & 63;
        float w = mlp_w2[n * 128 + k];
        __half h = __float2half_rn(w);
        g_w2th[i] = h;
        g_w2tl[i] = __float2half_rn(w - __half2float(h));
        return;
    }
    i -= 8192;
    if (i < 2048) {                     // w3t: [k=64][n=32]
        int k = i >> 5, n = i & 31;
        float w = mlp_w3[n * 64 + k];
        __half h = __float2half_rn(w);
        g_w3th[i] = h;
        g_w3tl[i] = __float2half_rn(w - __half2float(h));
    }
}

// ---------------------------------------------------------------------------
// k0: gathers -> split fp16 all_feat rows 0..119, plus base = b1 + Wc0@item
//     + sum_j Tc[j][:,kk] (fp32 -> g_base2).
// ---------------------------------------------------------------------------
extern "C" __global__ void __launch_bounds__(128, 4)
k0_feat(const int* __restrict__ userid, const int* __restrict__ itemid,
        const int* __restrict__ user_age, const int* __restrict__ gender,
        const int* __restrict__ user_occ, const int* __restrict__ item_kind,
        const float* __restrict__ user_emb, const float* __restrict__ item_emb,
        const float* __restrict__ age_emb, const float* __restrict__ gender_emb,
        const float* __restrict__ occ_emb, const float* __restrict__ kind_emb,
        const float* __restrict__ act_b1, int B)
{
    __shared__ float sWc0[64 * 8];
    for (int idx = threadIdx.x; idx < 512; idx += blockDim.x) sWc0[idx] = g_Wc0[idx];
    __syncthreads();

    int b = blockIdx.x * blockDim.x + threadIdx.x;
    if (b >= B) return;
    size_t sB = (size_t)B;

    float4 iv0, iv1;
    {
        const float* p = user_emb + (size_t)userid[b] * 8;
        st8(B, b, 0, ldg4(p), ldg4(p + 4));
        p = item_emb + (size_t)itemid[b] * 8;
        iv0 = ldg4(p); iv1 = ldg4(p + 4);
        st8(B, b, 4, iv0, iv1);
        p = age_emb + (size_t)user_age[b] * 8;
        st8(B, b, 8, ldg4(p), ldg4(p + 4));
        p = gender_emb + (size_t)gender[b] * 8;
        st8(B, b, 12, ldg4(p), ldg4(p + 4));
        p = occ_emb + (size_t)user_occ[b] * 8;
        st8(B, b, 16, ldg4(p), ldg4(p + 4));
    }

    float acc[64];
    #pragma unroll
    for (int o = 0; o < 64; o++) acc[o] = __ldg(act_b1 + o);

    #pragma unroll
    for (int o = 0; o < 64; o++) {
        float4 w0 = *(const float4*)(sWc0 + o * 8);
        float4 w1 = *(const float4*)(sWc0 + o * 8 + 4);
        acc[o] += w0.x*iv0.x + w0.y*iv0.y + w0.z*iv0.z + w0.w*iv0.w
                + w1.x*iv1.x + w1.y*iv1.y + w1.z*iv1.z + w1.w*iv1.w;
    }

    #pragma unroll 1
    for (int j = 0; j < 10; j++) {
        int kk = item_kind[b * KINDS + j];
        // kind feature rows (masked)
        const float* p = kind_emb + (size_t)kk * 8;
        float4 v0 = ldg4(p), v1 = ldg4(p + 4);
        if (kk == 0) { v0 = make_float4(0.f,0.f,0.f,0.f); v1 = v0; }
        st8(B, b, 20 + 4 * j, v0, v1);
        // base contribution via table
        const float4* t = (const float4*)g_Tc + (size_t)(j * 16) * 20 + kk;
        #pragma unroll
        for (int o4 = 0; o4 < 16; o4++) {
            float4 v = __ldg(t + o4 * 20);
            acc[4*o4+0] += v.x; acc[4*o4+1] += v.y;
            acc[4*o4+2] += v.z; acc[4*o4+3] += v.w;
        }
    }

    float2* bp = g_base2 + (size_t)b;
    #pragma unroll
    for (int o = 0; o < 32; o++)
        bp[(size_t)o * sB] = make_float2(acc[2*o], acc[2*o + 1]);
}

// ---------------------------------------------------------------------------
// k1s: all 5 attention scores (R9-proven scalar form).
// ---------------------------------------------------------------------------
extern "C" __global__ void __launch_bounds__(128, 4)
k1s_score(const int* __restrict__ his_id, const int* __restrict__ his_kind,
          const float* __restrict__ item_emb, const float* __restrict__ kind_emb,
          const float* __restrict__ act_w1,
          const float* __restrict__ act_w2, const float* __restrict__ act_b2,
          const float* __restrict__ act_w3, const float* __restrict__ act_b3,
          int B)
{
    __shared__ float sWa[64 * 88];
    __shared__ float sW2[32 * 64];
    __shared__ float sB2[32];
    __shared__ float sW3[32];
    __shared__ float sB3s;

    for (int idx = threadIdx.x; idx < 64 * 88; idx += blockDim.x) {
        int o = idx / 88, k = idx - o * 88;
        const float* r = act_w1 + o * 264;
        sWa[idx] = r[k] + r[88 + k];
    }
    for (int idx = threadIdx.x; idx < 32 * 64; idx += blockDim.x) sW2[idx] = act_w2[idx];
    if (threadIdx.x < 32) { sB2[threadIdx.x] = act_b2[threadIdx.x];
                            sW3[threadIdx.x] = act_w3[threadIdx.x]; }
    if (threadIdx.x == 0) sB3s = act_b3[0];
    __syncthreads();

    int b = blockIdx.x * blockDim.x + threadIdx.x;
    if (b >= B) return;
    size_t sB = (size_t)B;

    #pragma unroll 1
    for (int s = 0; s < HIS; s++) {
        float acc[64];
        {
            const float2* bp = g_base2 + (size_t)b;
            #pragma unroll
            for (int o = 0; o < 32; o++) {
                float2 v = bp[(size_t)o * sB];
                acc[2*o] = v.x; acc[2*o + 1] = v.y;
            }
        }

        int hid = his_id[b * HIS + s];
        #pragma unroll 1
        for (int j = 0; j < 11; j++) {
            float4 v0, v1;
            if (j == 0) {
                const float* p = item_emb + (size_t)hid * 8;
                v0 = ldg4(p); v1 = ldg4(p + 4);
            } else {
                int kk = his_kind[(b * HIS + s) * KINDS + (j - 1)];
                const float* p = kind_emb + (size_t)kk * 8;
                v0 = ldg4(p); v1 = ldg4(p + 4);
                float m = (kk != 0) ? 1.f : 0.f;
                v0.x*=m; v0.y*=m; v0.z*=m; v0.w*=m;
                v1.x*=m; v1.y*=m; v1.z*=m; v1.w*=m;
            }
            const float* wb = sWa + j * 8;
            #pragma unroll
            for (int o = 0; o < 64; o++) {
                float4 w0 = *(const float4*)(wb + o * 88);
                float4 w1 = *(const float4*)(wb + o * 88 + 4);
                acc[o] += w0.x*v0.x + w0.y*v0.y + w0.z*v0.z + w0.w*v0.w
                        + w1.x*v1.x + w1.y*v1.y + w1.z*v1.z + w1.w*v1.w;
            }
        }

        float acc2[32];
        #pragma unroll
        for (int o = 0; o < 32; o++) acc2[o] = sB2[o];
        #pragma unroll
        for (int kc = 0; kc < 16; kc++) {
            float a0 = fmaxf(acc[4*kc+0], 0.f);
            float a1 = fmaxf(acc[4*kc+1], 0.f);
            float a2 = fmaxf(acc[4*kc+2], 0.f);
            float a3 = fmaxf(acc[4*kc+3], 0.f);
            const float* wb = sW2 + 4 * kc;
            #pragma unroll
            for (int o = 0; o < 32; o++) {
                float4 w = *(const float4*)(wb + o * 64);
                acc2[o] += w.x*a0 + w.y*a1 + w.z*a2 + w.w*a3;
            }
        }
        float sc = sB3s;
        #pragma unroll
        for (int o = 0; o < 32; o++) sc += sW3[o] * fmaxf(acc2[o], 0.f);
        g_score[(size_t)s * sB + (size_t)b] = sc;
    }
}

// ---------------------------------------------------------------------------
// k2: his_pool -> split fp16 rows 120..207 (rowpairs 60..103).
// ---------------------------------------------------------------------------
extern "C" __global__ void __launch_bounds__(128, 4)
k2_pool(const int* __restrict__ his_id, const int* __restrict__ his_kind,
        const float* __restrict__ item_emb, const float* __restrict__ kind_emb,
        int B)
{
    int b = blockIdx.x * blockDim.x + threadIdx.x;
    if (b >= B) return;
    size_t sB = (size_t)B;

    float poolL[88];
    #pragma unroll
    for (int d = 0; d < 88; d++) poolL[d] = 0.f;

    #pragma unroll 1
    for (int s = 0; s < HIS; s++) {
        float sc = g_score[(size_t)s * sB + (size_t)b];
        int hid = his_id[b * HIS + s];
        {
            const float* p = item_emb + (size_t)hid * 8;
            float4 v0 = ldg4(p), v1 = ldg4(p + 4);
            poolL[0] += v0.x*v0.x*sc; poolL[1] += v0.y*v0.y*sc;
            poolL[2] += v0.z*v0.z*sc; poolL[3] += v0.w*v0.w*sc;
            poolL[4] += v1.x*v1.x*sc; poolL[5] += v1.y*v1.y*sc;
            poolL[6] += v1.z*v1.z*sc; poolL[7] += v1.w*v1.w*sc;
        }
        #pragma unroll
        for (int j = 0; j < 10; j++) {
            int kk = his_kind[(b * HIS + s) * KINDS + j];
            const float* p = kind_emb + (size_t)kk * 8;
            float4 v0 = ldg4(p), v1 = ldg4(p + 4);
            float fm = (kk != 0) ? sc : 0.f;
            int pp = 8 + j * 8;
            poolL[pp+0] += v0.x*v0.x*fm; poolL[pp+1] += v0.y*v0.y*fm;
            poolL[pp+2] += v0.z*v0.z*fm; poolL[pp+3] += v0.w*v0.w*fm;
            poolL[pp+4] += v1.x*v1.x*fm; poolL[pp+5] += v1.y*v1.y*fm;
            poolL[pp+6] += v1.z*v1.z*fm; poolL[pp+7] += v1.w*v1.w*fm;
        }
    }
    #pragma unroll 1
    for (int d = 0; d < 44; d++)
        st_feat(B, b, 60 + d, poolL[2*d], poolL[2*d + 1]);
}

// ---------------------------------------------------------------------------
// t2_mlp: fused 208->128->64->32->1 + sigmoid via split-fp16 wmma.
// Block: 512 threads (16 warps), 128 samples. Dynamic smem 157184 B.
// ---------------------------------------------------------------------------
#define T2_SMEM 157184

extern "C" __global__ void __launch_bounds__(512, 1)
t2_mlp(const float* __restrict__ mlp_b1, const float* __restrict__ mlp_b2,
       const float* __restrict__ mlp_b3, const float* __restrict__ mlp_w4,
       const float* __restrict__ mlp_b4, float* __restrict__ out, int B)
{
    extern __shared__ char smem[];
    __half* sAkH = (__half*)(smem + 0);        // [16][136]
    __half* sAkL = (__half*)(smem + 4352);
    __half* sBkH = (__half*)(smem + 8704);     // [16][136] (cols used vary)
    __half* sBkL = (__half*)(smem + 13056);
    __half* sA2H = (__half*)(smem + 17408);    // [128][136]
    __half* sA2L = (__half*)(smem + 52224);
    __half* sA3H = (__half*)(smem + 87040);    // [128][72]
    __half* sA3L = (__half*)(smem + 105472);
    float*  sScr = (float*)(smem + 123904);    // [16 warps][256]
    float*  sH3  = (float*)(smem + 140288);    // [128][33]

    int tid = threadIdx.x;
    int w = tid >> 5, lane = tid & 31;
    int m0 = blockIdx.x * 128;
    int mr = w >> 1;                 // row tile 0..7
    int m0w = mr * 16;
    float* scr = sScr + w * 256;

    typedef wmma::fragment<wmma::matrix_a, 16,16,16, __half, wmma::col_major> FragAc;
    typedef wmma::fragment<wmma::matrix_a, 16,16,16, __half, wmma::row_major> FragAr;
    typedef wmma::fragment<wmma::matrix_b, 16,16,16, __half, wmma::row_major> FragB;
    typedef wmma::fragment<wmma::accumulator, 16,16,16, float> FragC;

    // ================= Layer 1: [128x208]@[208x128] =================
    FragC acc[4];
    #pragma unroll
    for (int c = 0; c < 4; c++) wmma::fill_fragment(acc[c], 0.0f);
    int nb1 = (w & 1) * 4;

    #pragma unroll 1
    for (int t = 0; t < 13; t++) {
        __syncthreads();
        // stage A ktile: features 16t..16t+15 for 128 samples
        #pragma unroll
        for (int i = tid; i < 1024; i += 512) {
            int j = i >> 7, m = i & 127;
            size_t src = (size_t)(8 * t + j) * (size_t)B + (size_t)(m0 + m);
            __half2 vh = g_af2h[src];
            __half2 vl = g_af2l[src];
            sAkH[(2*j) * 136 + m]     = __low2half(vh);
            sAkH[(2*j + 1) * 136 + m] = __high2half(vh);
            sAkL[(2*j) * 136 + m]     = __low2half(vl);
            sAkL[(2*j + 1) * 136 + m] = __high2half(vl);
        }
        // stage B ktile: w1t rows 16t..16t+15, 128 cols
        #pragma unroll
        for (int i = tid; i < 1024; i += 512) {
            int kk = i >> 6, c2 = i & 63;
            *(__half2*)&sBkH[kk * 136 + 2 * c2] =
                ((const __half2*)g_w1th)[(16 * t + kk) * 64 + c2];
            *(__half2*)&sBkL[kk * 136 + 2 * c2] =
                ((const __half2*)g_w1tl)[(16 * t + kk) * 64 + c2];
        }
        __syncthreads();

        FragAc ah, al;
        wmma::load_matrix_sync(ah, sAkH + m0w, 136);
        wmma::load_matrix_sync(al, sAkL + m0w, 136);
        #pragma unroll
        for (int c = 0; c < 4; c++) {
            int n0 = (nb1 + c) * 16;
            FragB bh, bl;
            wmma::load_matrix_sync(bh, sBkH + n0, 136);
            wmma::load_matrix_sync(bl, sBkL + n0, 136);
            wmma::mma_sync(acc[c], ah, bh, acc[c]);
            wmma::mma_sync(acc[c], ah, bl, acc[c]);
            wmma::mma_sync(acc[c], al, bh, acc[c]);
        }
    }
    // epilogue L1: bias + relu + split -> sA2
    #pragma unroll 1
    for (int c = 0; c < 4; c++) {
        __syncwarp();
        wmma::store_matrix_sync(scr, acc[c], 16, wmma::mem_row_major);
        __syncwarp();
        int n0 = (nb1 + c) * 16;
        #pragma unroll
        for (int i = 0; i < 8; i++) {
            int idx = i * 32 + lane;
            int r = idx >> 4, cc = idx & 15;
            int n = n0 + cc, m = m0w + r;
            float v = scr[idx] + __ldg(mlp_b1 + n);
            v = fmaxf(v, 0.f);
            __half hv = __float2half_rn(v);
            sA2H[m * 136 + n] = hv;
            sA2L[m * 136 + n] = __float2half_rn(v - __half2float(hv));
        }
    }
    __syncthreads();

    // ================= Layer 2: [128x128]@[128x64] =================
    FragC acc2[2];
    #pragma unroll
    for (int c = 0; c < 2; c++) wmma::fill_fragment(acc2[c], 0.0f);
    int nb2 = (w & 1) * 2;

    #pragma unroll 1
    for (int t = 0; t < 8; t++) {
        __syncthreads();
        {
            int i = tid;
            if (i < 512) {
                int kk = i >> 5, c2 = i & 31;
                *(__half2*)&sBkH[kk * 136 + 2 * c2] =
                    ((const __half2*)g_w2th)[(16 * t + kk) * 32 + c2];
                *(__half2*)&sBkL[kk * 136 + 2 * c2] =
                    ((const __half2*)g_w2tl)[(16 * t + kk) * 32 + c2];
            }
        }
        __syncthreads();

        FragAr ah, al;
        wmma::load_matrix_sync(ah, sA2H + m0w * 136 + 16 * t, 136);
        wmma::load_matrix_sync(al, sA2L + m0w * 136 + 16 * t, 136);
        #pragma unroll
        for (int c = 0; c < 2; c++) {
            int n0 = (nb2 + c) * 16;
            FragB bh, bl;
            wmma::load_matrix_sync(bh, sBkH + n0, 136);
            wmma::load_matrix_sync(bl, sBkL + n0, 136);
            wmma::mma_sync(acc2[c], ah, bh, acc2[c]);
            wmma::mma_sync(acc2[c], ah, bl, acc2[c]);
            wmma::mma_sync(acc2[c], al, bh, acc2[c]);
        }
    }
    // epilogue L2 -> sA3
    #pragma unroll 1
    for (int c = 0; c < 2; c++) {
        __syncwarp();
        wmma::store_matrix_sync(scr, acc2[c], 16, wmma::mem_row_major);
        __syncwarp();
        int n0 = (nb2 + c) * 16;
        #pragma unroll
        for (int i = 0; i < 8; i++) {
            int idx = i * 32 + lane;
            int r = idx >> 4, cc = idx & 15;
            int n = n0 + cc, m = m0w + r;
            float v = scr[idx] + __ldg(mlp_b2 + n);
            v = fmaxf(v, 0.f);
            __half hv = __float2half_rn(v);
            sA3H[m * 72 + n] = hv;
            sA3L[m * 72 + n] = __float2half_rn(v - __half2float(hv));
        }
    }
    __syncthreads();

    // ================= Layer 3: [128x64]@[64x32] =================
    FragC acc3;
    wmma::fill_fragment(acc3, 0.0f);
    int n03 = (w & 1) * 16;

    #pragma unroll 1
    for (int t = 0; t < 4; t++) {
        __syncthreads();
        if (tid < 256) {
            int kk = tid >> 4, c2 = tid & 15;
            *(__half2*)&sBkH[kk * 136 + 2 * c2] =
                ((const __half2*)g_w3th)[(16 * t + kk) * 16 + c2];
            *(__half2*)&sBkL[kk * 136 + 2 * c2] =
                ((const __half2*)g_w3tl)[(16 * t + kk) * 16 + c2];
        }
        __syncthreads();

        FragAr ah, al;
        wmma::load_matrix_sync(ah, sA3H + m0w * 72 + 16 * t, 72);
        wmma::load_matrix_sync(al, sA3L + m0w * 72 + 16 * t, 72);
        FragB bh, bl;
        wmma::load_matrix_sync(bh, sBkH + n03, 136);
        wmma::load_matrix_sync(bl, sBkL + n03, 136);
        wmma::mma_sync(acc3, ah, bh, acc3);
        wmma::mma_sync(acc3, ah, bl, acc3);
        wmma::mma_sync(acc3, al, bh, acc3);
    }
    // epilogue L3: bias + relu -> sH3 fp32
    __syncwarp();
    wmma::store_matrix_sync(scr, acc3, 16, wmma::mem_row_major);
    __syncwarp();
    #pragma unroll
    for (int i = 0; i < 8; i++) {
        int idx = i * 32 + lane;
        int r = idx >> 4, cc = idx & 15;
        int n = n03 + cc, m = m0w + r;
        float v = scr[idx] + __ldg(mlp_b3 + n);
        sH3[m * 33 + n] = fmaxf(v, 0.f);
    }
    __syncthreads();

    // ================= Layer 4 + sigmoid =================
    if (tid < 128) {
        int m = tid;
        float logit = __ldg(mlp_b4);
        #pragma unroll
        for (int o = 0; o < 32; o++)
            logit += __ldg(mlp_w4 + o) * sH3[m * 33 + o];
        out[m0 + m] = 1.f / (1.f + expf(-logit));
    }
}

// ---------------------------------------------------------------------------
extern "C" void kernel_launch(void* const* d_in, const int* in_sizes, int n_in,
                              void* d_out, int out_size)
{
    const int*   userid   = (const int*)d_in[0];
    const int*   itemid   = (const int*)d_in[1];
    const int*   user_age = (const int*)d_in[2];
    const int*   gender   = (const int*)d_in[3];
    const int*   user_occ = (const int*)d_in[4];
    const int*   item_kind= (const int*)d_in[5];
    const int*   his_id   = (const int*)d_in[6];
    const int*   his_kind = (const int*)d_in[7];
    const float* user_emb = (const float*)d_in[8];
    const float* item_emb = (const float*)d_in[9];
    const float* age_emb  = (const float*)d_in[10];
    const float* gen_emb  = (const float*)d_in[11];
    const float* occ_emb  = (const float*)d_in[12];
    const float* kind_emb = (const float*)d_in[13];
    const float* act_w1 = (const float*)d_in[14];
    const float* act_b1 = (const float*)d_in[15];
    const float* act_w2 = (const float*)d_in[16];
    const float* act_b2 = (const float*)d_in[17];
    const float* act_w3 = (const float*)d_in[18];
    const float* act_b3 = (const float*)d_in[19];
    const float* mlp_w1 = (const float*)d_in[20];
    const float* mlp_b1 = (const float*)d_in[21];
    const float* mlp_w2 = (const float*)d_in[22];
    const float* mlp_b2 = (const float*)d_in[23];
    const float* mlp_w3 = (const float*)d_in[24];
    const float* mlp_b3 = (const float*)d_in[25];
    const float* mlp_w4 = (const float*)d_in[26];
    const float* mlp_b4 = (const float*)d_in[27];

    int B = in_sizes[0];
    int nb = (B + 127) / 128;

    // Opt in to >48KB dynamic smem for t2_mlp (idempotent, capture-safe).
    cudaFuncSetAttribute((const void*)t2_mlp,
                         cudaFuncAttributeMaxDynamicSharedMemorySize, T2_SMEM);

    prep_tables<<<196, 256>>>(act_w1, mlp_w1, mlp_w2, mlp_w3, kind_emb);

    k0_feat<<<nb, 128>>>(userid, itemid, user_age, gender, user_occ, item_kind,
                         user_emb, item_emb, age_emb, gen_emb, occ_emb, kind_emb,
                         act_b1, B);

    k1s_score<<<nb, 128>>>(his_id, his_kind, item_emb, kind_emb, act_w1,
                           act_w2, act_b2, act_w3, act_b3, B);

    k2_pool<<<nb, 128>>>(his_id, his_kind, item_emb, kind_emb, B);

    t2_mlp<<<nb, 512, T2_SMEM>>>(mlp_b1, mlp_b2, mlp_b3, mlp_w4, mlp_b4,
                                 (float*)d_out, B);
}